// round 1
// baseline (speedup 1.0000x reference)
#include <cuda_runtime.h>
#include <cuda_bf16.h>
#include <math.h>

// ---------------- problem constants ----------------
#define BB   16
#define NN   4096
#define SS   512
#define DD2  384
#define KNN  5
#define MM   (BB*NN)          // 65536 rows
#define LDA  392              // padded K stride for A scratch (387 -> 392, mult of 8)
#define K0   392              // gemm0 K (padded, pad cols are zero)
#define K1   384              // gemm1 K
#define OC   384              // output channels
#define X_ELEMS ((size_t)MM*DD2)   // 25165824
#define EPSF 1.1920929e-7f

// ---------------- device scratch (static, no allocation) ----------------
__device__ float g_A[(size_t)MM * LDA];      // new_points padded / gelu activations
__device__ float g_X0[(size_t)MM * DD2];     // gemm0 raw output
__device__ float g_Wt0[K0 * OC];             // W0 transposed+padded: [392][384]
__device__ float g_Wt1[K1 * OC];             // W1 transposed: [384][384]
__device__ int   g_idx[MM * KNN];
__device__ float g_w[MM * KNN];
__device__ float g_part[512 * 2 * DD2];      // per-chunk (sum, sumsq) partials
__device__ float g_scale[2 * DD2];
__device__ float g_shift[2 * DD2];

// ---------------- helpers ----------------
__device__ __forceinline__ void ffma2(unsigned long long &d,
                                      const unsigned long long a,
                                      const unsigned long long b) {
    asm("fma.rn.f32x2 %0, %1, %2, %0;" : "+l"(d) : "l"(a), "l"(b));
}
__device__ __forceinline__ unsigned long long dup2(float x) {
    unsigned long long r; asm("mov.b64 %0, {%1, %1};" : "=l"(r) : "f"(x)); return r;
}
__device__ __forceinline__ void unpack2(unsigned long long v, float &lo, float &hi) {
    asm("mov.b64 {%0, %1}, %2;" : "=f"(lo), "=f"(hi) : "l"(v));
}
__device__ __forceinline__ float gelu_exact(float v) {
    return 0.5f * v * (1.0f + erff(v * 0.7071067811865476f));
}

// ---------------- K0: transpose+pad weights ----------------
__global__ void prep_weights_kernel(const float* __restrict__ W0,
                                    const float* __restrict__ W1) {
    int i = blockIdx.x * blockDim.x + threadIdx.x;
    if (i < K0 * OC) {
        int k = i / OC, o = i % OC;
        g_Wt0[i] = (k < 387) ? W0[o * 387 + k] : 0.0f;
    }
    if (i < K1 * OC) {
        int k = i / OC, o = i % OC;
        g_Wt1[i] = W1[o * OC + k];
    }
}

// ---------------- K1: KNN (top-5 smallest squared distance) ----------------
__global__ void knn_kernel(const float* __restrict__ xyz1,
                           const float* __restrict__ xyz2,
                           const int* __restrict__ elens,
                           float* __restrict__ out_idx) {
    __shared__ float sx[SS], sy[SS], sz[SS];
    int b = blockIdx.y;
    const float* x2 = xyz2 + (size_t)b * SS * 3;
    for (int i = threadIdx.x; i < SS; i += blockDim.x) {
        sx[i] = x2[i * 3 + 0];
        sy[i] = x2[i * 3 + 1];
        sz[i] = x2[i * 3 + 2];
    }
    __syncthreads();

    int n = blockIdx.x * blockDim.x + threadIdx.x;
    int row = b * NN + n;
    float px = xyz1[(size_t)row * 3 + 0];
    float py = xyz1[(size_t)row * 3 + 1];
    float pz = xyz1[(size_t)row * 3 + 2];
    int sv = elens[b];

    float b0 = 1e30f, b1 = 1e30f, b2 = 1e30f, b3 = 1e30f, b4 = 1e30f;
    int   j0 = 0, j1 = 0, j2 = 0, j3 = 0, j4 = 0;

    for (int s = 0; s < sv; ++s) {
        float dx = px - sx[s];
        float dy = py - sy[s];
        float dz = pz - sz[s];
        float d = __fmaf_rn(dz, dz, __fmaf_rn(dy, dy, dx * dx));
        if (d < b4) {
            if (d < b3) {
                b4 = b3; j4 = j3;
                if (d < b2) {
                    b3 = b2; j3 = j2;
                    if (d < b1) {
                        b2 = b1; j2 = j1;
                        if (d < b0) { b1 = b0; j1 = j0; b0 = d; j0 = s; }
                        else        { b1 = d;  j1 = s; }
                    } else { b2 = d; j2 = s; }
                } else { b3 = d; j3 = s; }
            } else { b4 = d; j4 = s; }
        }
    }

    float r0 = 1.0f / (b0 + EPSF);
    float r1 = 1.0f / (b1 + EPSF);
    float r2 = 1.0f / (b2 + EPSF);
    float r3 = 1.0f / (b3 + EPSF);
    float r4 = 1.0f / (b4 + EPSF);
    float rsum = ((((r0 + r1) + r2) + r3) + r4);

    size_t base = (size_t)row * KNN;
    g_idx[base + 0] = j0; g_idx[base + 1] = j1; g_idx[base + 2] = j2;
    g_idx[base + 3] = j3; g_idx[base + 4] = j4;
    g_w[base + 0] = r0 / rsum; g_w[base + 1] = r1 / rsum; g_w[base + 2] = r2 / rsum;
    g_w[base + 3] = r3 / rsum; g_w[base + 4] = r4 / rsum;
    out_idx[base + 0] = (float)j0; out_idx[base + 1] = (float)j1;
    out_idx[base + 2] = (float)j2; out_idx[base + 3] = (float)j3;
    out_idx[base + 4] = (float)j4;
}

// ---------------- K2: interpolation + concat -> g_A ----------------
__global__ void interp_kernel(const float* __restrict__ points1,
                              const float* __restrict__ points2) {
    int gwarp = (blockIdx.x * blockDim.x + threadIdx.x) >> 5;
    int lane = threadIdx.x & 31;
    if (gwarp >= MM) return;
    int row = gwarp;
    int b = row >> 12;

    const int* ip = g_idx + (size_t)row * KNN;
    const float* wp = g_w + (size_t)row * KNN;
    int i0 = ip[0], i1 = ip[1], i2 = ip[2], i3 = ip[3], i4 = ip[4];
    float w0 = wp[0], w1 = wp[1], w2 = wp[2], w3 = wp[3], w4 = wp[4];

    const float* p2 = points2 + (size_t)b * SS * DD2;
    const float* r0 = p2 + (size_t)i0 * DD2;
    const float* r1 = p2 + (size_t)i1 * DD2;
    const float* r2 = p2 + (size_t)i2 * DD2;
    const float* r3 = p2 + (size_t)i3 * DD2;
    const float* r4 = p2 + (size_t)i4 * DD2;

    float* out = g_A + (size_t)row * LDA;
#pragma unroll
    for (int cc = 0; cc < DD2 / 32; ++cc) {
        int c = cc * 32 + lane;
        float acc = w0 * r0[c];
        acc = __fmaf_rn(w1, r1[c], acc);
        acc = __fmaf_rn(w2, r2[c], acc);
        acc = __fmaf_rn(w3, r3[c], acc);
        acc = __fmaf_rn(w4, r4[c], acc);
        out[3 + c] = acc;
    }
    if (lane < 3)  out[lane] = points1[(size_t)row * 3 + lane];
    if (lane >= 27) out[360 + lane] = 0.0f;   // pad cols 387..391
}

// ---------------- SGEMM: C[M,384] = A[M,kdim] * Bt[kdim,384] (f32x2) -----
__global__ __launch_bounds__(256, 2)
void sgemm_kernel(const float* __restrict__ A, int kdim,
                  const float* __restrict__ Bt, float* __restrict__ C) {
    __shared__ __align__(16) float As[2][8][132];
    __shared__ __align__(16) float Bs[2][8][128];

    int mbase = blockIdx.y * 128;
    int obase = blockIdx.x * 128;
    int tid = threadIdx.x;
    int tx = tid & 15, ty = tid >> 4;

    int ar = tid >> 1;              // 0..127
    int ak = (tid & 1) * 4;         // 0 or 4
    const float* Aptr = A + (size_t)(mbase + ar) * LDA + ak;

    int bk = tid >> 5;              // 0..7
    int bo = (tid & 31) * 4;        // 0..124
    const float* Bptr = Bt + (size_t)bk * OC + obase + bo;

    int ntiles = kdim >> 3;

    float4 aReg = *(const float4*)(Aptr);
    float4 bReg = *(const float4*)(Bptr);
    As[0][ak + 0][ar] = aReg.x;
    As[0][ak + 1][ar] = aReg.y;
    As[0][ak + 2][ar] = aReg.z;
    As[0][ak + 3][ar] = aReg.w;
    *(float4*)&Bs[0][bk][bo] = bReg;
    __syncthreads();

    unsigned long long acc[4][8];
#pragma unroll
    for (int i = 0; i < 4; ++i)
#pragma unroll
        for (int j = 0; j < 8; ++j) acc[i][j] = 0ULL;

    int buf = 0;
    for (int t = 0; t < ntiles; ++t) {
        if (t + 1 < ntiles) {
            aReg = *(const float4*)(Aptr + (t + 1) * 8);
            bReg = *(const float4*)(Bptr + (size_t)(t + 1) * 8 * OC);
        }
#pragma unroll
        for (int kk = 0; kk < 8; ++kk) {
            ulonglong2 aa0 = *(const ulonglong2*)&As[buf][kk][ty * 8];
            ulonglong2 aa1 = *(const ulonglong2*)&As[buf][kk][ty * 8 + 4];
            float4 b0 = *(const float4*)&Bs[buf][kk][tx * 8];
            float4 b1 = *(const float4*)&Bs[buf][kk][tx * 8 + 4];
            unsigned long long ap[4] = { aa0.x, aa0.y, aa1.x, aa1.y };
            unsigned long long bb[8];
            bb[0] = dup2(b0.x); bb[1] = dup2(b0.y); bb[2] = dup2(b0.z); bb[3] = dup2(b0.w);
            bb[4] = dup2(b1.x); bb[5] = dup2(b1.y); bb[6] = dup2(b1.z); bb[7] = dup2(b1.w);
#pragma unroll
            for (int i = 0; i < 4; ++i)
#pragma unroll
                for (int j = 0; j < 8; ++j)
                    ffma2(acc[i][j], ap[i], bb[j]);
        }
        if (t + 1 < ntiles) {
            int nb = buf ^ 1;
            As[nb][ak + 0][ar] = aReg.x;
            As[nb][ak + 1][ar] = aReg.y;
            As[nb][ak + 2][ar] = aReg.z;
            As[nb][ak + 3][ar] = aReg.w;
            *(float4*)&Bs[nb][bk][bo] = bReg;
            __syncthreads();
            buf = nb;
        }
    }

    // epilogue: acc[i] holds rows (ty*8+2i, ty*8+2i+1)
#pragma unroll
    for (int i = 0; i < 4; ++i) {
        float lo[8], hi[8];
#pragma unroll
        for (int j = 0; j < 8; ++j) unpack2(acc[i][j], lo[j], hi[j]);
        float* crow = C + (size_t)(mbase + ty * 8 + 2 * i) * OC + obase + tx * 8;
        float4 e;
        e.x = lo[0]; e.y = lo[1]; e.z = lo[2]; e.w = lo[3]; *(float4*)(crow) = e;
        e.x = lo[4]; e.y = lo[5]; e.z = lo[6]; e.w = lo[7]; *(float4*)(crow + 4) = e;
        crow += OC;
        e.x = hi[0]; e.y = hi[1]; e.z = hi[2]; e.w = hi[3]; *(float4*)(crow) = e;
        e.x = hi[4]; e.y = hi[5]; e.z = hi[6]; e.w = hi[7]; *(float4*)(crow + 4) = e;
    }
}

// ---------------- stats: per-chunk masked (sum, sumsq) per channel -------
__global__ void stats_kernel(const float* __restrict__ X,
                             const int* __restrict__ plens) {
    int c = threadIdx.x;                 // 0..383
    int chunk = blockIdx.x;              // 512 chunks of 128 rows
    int r0 = chunk * 128;
    int b = r0 >> 12;
    int lim = plens[b] - (r0 & 4095);
    int nv = lim < 0 ? 0 : (lim > 128 ? 128 : lim);
    const float* p = X + (size_t)r0 * DD2 + c;
    float s = 0.0f, s2 = 0.0f;
    for (int r = 0; r < nv; ++r) {
        float x = p[(size_t)r * DD2];
        s += x;
        s2 = __fmaf_rn(x, x, s2);
    }
    g_part[(size_t)chunk * 768 + c] = s;
    g_part[(size_t)chunk * 768 + 384 + c] = s2;
}

// ---------------- finalize: mean/var -> scale/shift ----------------------
__global__ void finalize_kernel(const float* __restrict__ gamma,
                                const float* __restrict__ beta,
                                const int* __restrict__ plens,
                                int layer) {
    int c = threadIdx.x;   // 384 threads, 1 block
    double s = 0.0, s2 = 0.0;
    for (int i = 0; i < 512; ++i) {
        s  += (double)g_part[(size_t)i * 768 + c];
        s2 += (double)g_part[(size_t)i * 768 + 384 + c];
    }
    float nf = 0.0f;
    for (int b = 0; b < BB; ++b) nf += (float)plens[b];
    nf = fmaxf(nf, 1.0f);
    float mean = (float)(s / (double)nf);
    float var = (float)(s2 / (double)nf) - mean * mean;
    var = fmaxf(var, 0.0f);
    float rs = rsqrtf(var + 1e-5f);
    float sc = gamma[c] * rs;
    g_scale[layer * DD2 + c] = sc;
    g_shift[layer * DD2 + c] = beta[c] - mean * sc;
}

// ---------------- BN apply (+optional GELU) ------------------------------
template <int DO_GELU>
__global__ void bn_apply_kernel(const float* __restrict__ X,
                                float* __restrict__ Y, int ldy,
                                const int* __restrict__ plens,
                                int layer) {
    size_t i4 = ((size_t)blockIdx.x * blockDim.x + threadIdx.x) * 4;
    if (i4 >= X_ELEMS) return;
    int row = (int)(i4 / DD2);
    int c = (int)(i4 % DD2);
    bool valid = (row & 4095) < plens[row >> 12];
    const float* sc = g_scale + layer * DD2 + c;
    const float* sh = g_shift + layer * DD2 + c;
    float4 x = *(const float4*)(X + i4);
    float4 y;
    if (valid) {
        y.x = __fmaf_rn(x.x, sc[0], sh[0]);
        y.y = __fmaf_rn(x.y, sc[1], sh[1]);
        y.z = __fmaf_rn(x.z, sc[2], sh[2]);
        y.w = __fmaf_rn(x.w, sc[3], sh[3]);
        if (DO_GELU) {
            y.x = gelu_exact(y.x); y.y = gelu_exact(y.y);
            y.z = gelu_exact(y.z); y.w = gelu_exact(y.w);
        }
    } else {
        y.x = 0.0f; y.y = 0.0f; y.z = 0.0f; y.w = 0.0f;
    }
    *(float4*)(Y + (size_t)row * ldy + c) = y;
}

// ---------------- launch ----------------
extern "C" void kernel_launch(void* const* d_in, const int* in_sizes, int n_in,
                              void* d_out, int out_size) {
    const float* xyz1    = (const float*)d_in[0];
    const float* xyz2    = (const float*)d_in[1];
    const float* points1 = (const float*)d_in[2];
    const float* points2 = (const float*)d_in[3];
    const int*   plens   = (const int*)d_in[4];
    const int*   elens   = (const int*)d_in[5];
    // d_in[6] = point_mask (recomputed from plens)
    const float* W0 = (const float*)d_in[7];
    const float* g0 = (const float*)d_in[8];
    const float* b0 = (const float*)d_in[9];
    const float* W1 = (const float*)d_in[10];
    const float* g1 = (const float*)d_in[11];
    const float* b1 = (const float*)d_in[12];
    float* out = (float*)d_out;

    float *pA, *pX0, *pWt0, *pWt1;
    cudaGetSymbolAddress((void**)&pA, g_A);
    cudaGetSymbolAddress((void**)&pX0, g_X0);
    cudaGetSymbolAddress((void**)&pWt0, g_Wt0);
    cudaGetSymbolAddress((void**)&pWt1, g_Wt1);

    prep_weights_kernel<<<(K0 * OC + 255) / 256, 256>>>(W0, W1);
    knn_kernel<<<dim3(NN / 256, BB), 256>>>(xyz1, xyz2, elens, out + X_ELEMS);
    interp_kernel<<<MM / 8, 256>>>(points1, points2);

    // GEMM0: x0 = new_points @ W0^T
    sgemm_kernel<<<dim3(3, MM / 128), 256>>>(pA, K0, pWt0, pX0);
    stats_kernel<<<512, 384>>>(pX0, plens);
    finalize_kernel<<<1, 384>>>(g0, b0, plens, 0);
    // a1 = gelu(bn0(x0)) (masked) -> g_A (stride LDA)
    bn_apply_kernel<1><<<(unsigned)(X_ELEMS / 4 + 255) / 256, 256>>>(pX0, pA, LDA, plens, 0);

    // GEMM1: x1 = a1 @ W1^T -> d_out (raw)
    sgemm_kernel<<<dim3(3, MM / 128), 256>>>(pA, K1, pWt1, out);
    stats_kernel<<<512, 384>>>(out, plens);
    finalize_kernel<<<1, 384>>>(g1, b1, plens, 1);
    // final masked BN1 in-place on d_out
    bn_apply_kernel<0><<<(unsigned)(X_ELEMS / 4 + 255) / 256, 256>>>(out, out, DD2, plens, 1);
}

// round 5
// speedup vs baseline: 2.6010x; 2.6010x over previous
#include <cuda_runtime.h>
#include <cuda_bf16.h>
#include <math.h>
#include <stdint.h>

// ---------------- problem constants ----------------
#define BB   16
#define NN   4096
#define SS   512
#define DD2  384
#define KNN  5
#define MM   (BB*NN)          // 65536 rows
#define KPAD 448              // padded K stride (bf16 arrays), mult of 32
#define OC   384              // output channels
#define X_ELEMS ((size_t)MM*DD2)   // 25165824
#define EPSF 1.1920929e-7f

// K-order permutation: k 0..383 = interpolated feature k, k 384..386 = xyz, 387.. = 0.
// Weights permuted identically, so the GEMM result is unchanged.

// ---------------- device scratch (static, no allocation) ----------------
__device__ __align__(128) __nv_bfloat16 g_Ah[(size_t)MM * KPAD];
__device__ __align__(128) __nv_bfloat16 g_Al[(size_t)MM * KPAD];
__device__ __align__(128) float g_X0[(size_t)MM * DD2];
__device__ __align__(128) __nv_bfloat16 g_W0h[OC * KPAD];
__device__ __align__(128) __nv_bfloat16 g_W0l[OC * KPAD];
__device__ __align__(128) __nv_bfloat16 g_W1h[OC * KPAD];
__device__ __align__(128) __nv_bfloat16 g_W1l[OC * KPAD];
__device__ int   g_idx[MM * KNN];
__device__ float g_w[MM * KNN];
__device__ float g_part[512 * 2 * DD2];
__device__ float g_scale[2 * DD2];
__device__ float g_shift[2 * DD2];

// ---------------- helpers ----------------
__device__ __forceinline__ uint32_t smem_u32(const void* p) {
    uint32_t a;
    asm("{ .reg .u64 t; cvta.to.shared.u64 t, %1; cvt.u32.u64 %0, t; }" : "=r"(a) : "l"(p));
    return a;
}
__device__ __forceinline__ void cp16(uint32_t s, const void* g) {
    asm volatile("cp.async.cg.shared.global [%0], [%1], 16;" :: "r"(s), "l"(g));
}
#define CP_COMMIT() asm volatile("cp.async.commit_group;")
#define CP_WAIT1()  asm volatile("cp.async.wait_group 1;")
#define CP_WAITALL() asm volatile("cp.async.wait_all;")

#define LDSM4(r, addr) \
    asm volatile("ldmatrix.sync.aligned.m8n8.x4.shared.b16 {%0,%1,%2,%3}, [%4];" \
        : "=r"((r)[0]), "=r"((r)[1]), "=r"((r)[2]), "=r"((r)[3]) : "r"(addr))

__device__ __forceinline__ void mma16816(float* c, const uint32_t* a, const uint32_t* b) {
    asm volatile(
        "mma.sync.aligned.m16n8k16.row.col.f32.bf16.bf16.f32 "
        "{%0,%1,%2,%3}, {%4,%5,%6,%7}, {%8,%9}, {%0,%1,%2,%3};"
        : "+f"(c[0]), "+f"(c[1]), "+f"(c[2]), "+f"(c[3])
        : "r"(a[0]), "r"(a[1]), "r"(a[2]), "r"(a[3]), "r"(b[0]), "r"(b[1]));
}

__device__ __forceinline__ float gelu_exact(float v) {
    return 0.5f * v * (1.0f + erff(v * 0.7071067811865476f));
}
__device__ __forceinline__ void split_bf16(float v, __nv_bfloat16 &h, __nv_bfloat16 &l) {
    h = __float2bfloat16(v);
    l = __float2bfloat16(v - __bfloat162float(h));
}

// ---------------- weight prep: permute + split + pad ----------------
__global__ void prep_weights_kernel(const float* __restrict__ W0,
                                    const float* __restrict__ W1) {
    int i = blockIdx.x * blockDim.x + threadIdx.x;
    if (i >= OC * KPAD) return;
    int o = i / KPAD, k = i % KPAD;
    float v0 = 0.0f, v1 = 0.0f;
    if (k < 384)      v0 = W0[o * 387 + 3 + k];   // feature part
    else if (k < 387) v0 = W0[o * 387 + (k - 384)]; // xyz part
    if (k < 384)      v1 = W1[o * 384 + k];
    __nv_bfloat16 h, l;
    split_bf16(v0, h, l); g_W0h[i] = h; g_W0l[i] = l;
    split_bf16(v1, h, l); g_W1h[i] = h; g_W1l[i] = l;
}

// ---------------- KNN ----------------
__global__ void knn_kernel(const float* __restrict__ xyz1,
                           const float* __restrict__ xyz2,
                           const int* __restrict__ elens,
                           float* __restrict__ out_idx) {
    __shared__ float sx[SS], sy[SS], sz[SS];
    int b = blockIdx.y;
    const float* x2 = xyz2 + (size_t)b * SS * 3;
    for (int i = threadIdx.x; i < SS; i += blockDim.x) {
        sx[i] = x2[i * 3 + 0]; sy[i] = x2[i * 3 + 1]; sz[i] = x2[i * 3 + 2];
    }
    __syncthreads();
    int n = blockIdx.x * blockDim.x + threadIdx.x;
    int row = b * NN + n;
    float px = xyz1[(size_t)row * 3 + 0];
    float py = xyz1[(size_t)row * 3 + 1];
    float pz = xyz1[(size_t)row * 3 + 2];
    int sv = elens[b];
    float b0 = 1e30f, b1 = 1e30f, b2 = 1e30f, b3 = 1e30f, b4 = 1e30f;
    int j0 = 0, j1 = 0, j2 = 0, j3 = 0, j4 = 0;
    for (int s = 0; s < sv; ++s) {
        float dx = px - sx[s], dy = py - sy[s], dz = pz - sz[s];
        float d = __fmaf_rn(dz, dz, __fmaf_rn(dy, dy, dx * dx));
        if (d < b4) {
            if (d < b3) {
                b4 = b3; j4 = j3;
                if (d < b2) {
                    b3 = b2; j3 = j2;
                    if (d < b1) {
                        b2 = b1; j2 = j1;
                        if (d < b0) { b1 = b0; j1 = j0; b0 = d; j0 = s; }
                        else        { b1 = d;  j1 = s; }
                    } else { b2 = d; j2 = s; }
                } else { b3 = d; j3 = s; }
            } else { b4 = d; j4 = s; }
        }
    }
    float r0 = 1.0f / (b0 + EPSF), r1 = 1.0f / (b1 + EPSF), r2 = 1.0f / (b2 + EPSF);
    float r3 = 1.0f / (b3 + EPSF), r4 = 1.0f / (b4 + EPSF);
    float rsum = r0 + r1 + r2 + r3 + r4;
    size_t base = (size_t)row * KNN;
    g_idx[base + 0] = j0; g_idx[base + 1] = j1; g_idx[base + 2] = j2;
    g_idx[base + 3] = j3; g_idx[base + 4] = j4;
    g_w[base + 0] = r0 / rsum; g_w[base + 1] = r1 / rsum; g_w[base + 2] = r2 / rsum;
    g_w[base + 3] = r3 / rsum; g_w[base + 4] = r4 / rsum;
    out_idx[base + 0] = (float)j0; out_idx[base + 1] = (float)j1;
    out_idx[base + 2] = (float)j2; out_idx[base + 3] = (float)j3;
    out_idx[base + 4] = (float)j4;
}

// ---------------- interpolation + concat -> g_Ah/g_Al (bf16 split) -------
__global__ void interp_kernel(const float* __restrict__ points1,
                              const float* __restrict__ points2) {
    int gwarp = (blockIdx.x * blockDim.x + threadIdx.x) >> 5;
    int lane = threadIdx.x & 31;
    if (gwarp >= MM) return;
    int row = gwarp;
    int b = row >> 12;
    const int* ip = g_idx + (size_t)row * KNN;
    const float* wp = g_w + (size_t)row * KNN;
    int i0 = ip[0], i1 = ip[1], i2 = ip[2], i3 = ip[3], i4 = ip[4];
    float w0 = wp[0], w1 = wp[1], w2 = wp[2], w3 = wp[3], w4 = wp[4];
    const float* p2 = points2 + (size_t)b * SS * DD2;
    const float2* r0 = (const float2*)(p2 + (size_t)i0 * DD2);
    const float2* r1 = (const float2*)(p2 + (size_t)i1 * DD2);
    const float2* r2 = (const float2*)(p2 + (size_t)i2 * DD2);
    const float2* r3 = (const float2*)(p2 + (size_t)i3 * DD2);
    const float2* r4 = (const float2*)(p2 + (size_t)i4 * DD2);
    __nv_bfloat16* oh = g_Ah + (size_t)row * KPAD;
    __nv_bfloat16* ol = g_Al + (size_t)row * KPAD;
    __nv_bfloat162* oh2 = (__nv_bfloat162*)oh;
    __nv_bfloat162* ol2 = (__nv_bfloat162*)ol;
#pragma unroll
    for (int cc = 0; cc < 6; ++cc) {
        int c2 = cc * 32 + lane;        // float2 index: cols 2*c2, 2*c2+1
        float2 v0 = r0[c2], v1 = r1[c2], v2 = r2[c2], v3 = r3[c2], v4 = r4[c2];
        float ax = w0 * v0.x; ax = __fmaf_rn(w1, v1.x, ax); ax = __fmaf_rn(w2, v2.x, ax);
        ax = __fmaf_rn(w3, v3.x, ax); ax = __fmaf_rn(w4, v4.x, ax);
        float ay = w0 * v0.y; ay = __fmaf_rn(w1, v1.y, ay); ay = __fmaf_rn(w2, v2.y, ay);
        ay = __fmaf_rn(w3, v3.y, ay); ay = __fmaf_rn(w4, v4.y, ay);
        __nv_bfloat16 hx, lx, hy, ly;
        split_bf16(ax, hx, lx); split_bf16(ay, hy, ly);
        oh2[c2] = __nv_bfloat162{hx, hy};
        ol2[c2] = __nv_bfloat162{lx, ly};
    }
    if (lane < 3) {   // xyz at k = 384..386
        float v = points1[(size_t)row * 3 + lane];
        __nv_bfloat16 h, l; split_bf16(v, h, l);
        oh[384 + lane] = h; ol[384 + lane] = l;
    }
    for (int c = 387 + lane; c < KPAD; c += 32) {
        oh[c] = __float2bfloat16(0.0f); ol[c] = __float2bfloat16(0.0f);
    }
}

// ---------------- bf16x3 GEMM via mma.sync (sm_80 path) ------------------
// C[M,384] = A[M,nk] * B^T.  CTA tile 128x128, warp 64x32, KC=32, 3 stages.
#define STAGE_SZ 32768
#define GEMM_SMEM (3*STAGE_SZ)

__global__ __launch_bounds__(256)
void gemm_mma_kernel(const __nv_bfloat16* __restrict__ Ahp,
                     const __nv_bfloat16* __restrict__ Alp,
                     const __nv_bfloat16* __restrict__ Bhp,
                     const __nv_bfloat16* __restrict__ Blp,
                     float* __restrict__ X, int nk) {
    extern __shared__ __align__(128) char smem[];
    uint32_t sb = smem_u32(smem);
    int tid = threadIdx.x, lane = tid & 31, wid = tid >> 5;
    int wm = wid & 1, wn = wid >> 1;
    int mbase = blockIdx.y * 128, nbase = blockIdx.x * 128;
    int nst = nk >> 5;

    int lrow = tid >> 2, lc = tid & 3;

    auto load_stage = [&](int st) {
        int slot = st % 3;
        uint32_t sA = sb + slot * STAGE_SZ;
        int kb = st * 32;
#pragma unroll
        for (int i = 0; i < 2; ++i) {
            int row = lrow + i * 64;
            uint32_t so = row * 64 + ((uint32_t)(lc ^ ((row >> 1) & 3)) << 4);
            size_t ga = (size_t)(mbase + row) * KPAD + kb + lc * 8;
            size_t gb = (size_t)(nbase + row) * KPAD + kb + lc * 8;
            cp16(sA + so,         Ahp + ga);
            cp16(sA + 8192 + so,  Alp + ga);
            cp16(sA + 16384 + so, Bhp + gb);
            cp16(sA + 24576 + so, Blp + gb);
        }
    };

    float acc[4][4][4] = {};

    load_stage(0); CP_COMMIT();
    load_stage(1); CP_COMMIT();

    int arow = lane & 15;            // A: row within m16 tile
    int ahalf = lane >> 4;           // A: k-chunk half
    int brow = (lane & 7) + ((lane >> 4) << 3);  // B: n within 16 (two n8 tiles)
    int bhalf = (lane >> 3) & 1;     // B: k-chunk half

    for (int st = 0; st < nst; ++st) {
        CP_WAIT1();
        __syncthreads();
        if (st + 2 < nst) load_stage(st + 2);
        CP_COMMIT();
        int slot = st % 3;
        uint32_t sA = sb + slot * STAGE_SZ;
        uint32_t sAl = sA + 8192, sB = sA + 16384, sBl = sA + 24576;
#pragma unroll
        for (int k2 = 0; k2 < 2; ++k2) {
            int cbase = 2 * k2;
            uint32_t ah[4][4], al[4][4], bh[2][4], bl[2][4];
            uint32_t aso[4], bso[2];
#pragma unroll
            for (int mi = 0; mi < 4; ++mi) {
                int row = wm * 64 + mi * 16 + arow;
                aso[mi] = row * 64 + ((uint32_t)((cbase + ahalf) ^ ((row >> 1) & 3)) << 4);
                LDSM4(ah[mi], sA + aso[mi]);
            }
#pragma unroll
            for (int g = 0; g < 2; ++g) {
                int row = wn * 32 + g * 16 + brow;
                bso[g] = row * 64 + ((uint32_t)((cbase + bhalf) ^ ((row >> 1) & 3)) << 4);
                LDSM4(bh[g], sB + bso[g]);
            }
#pragma unroll
            for (int mi = 0; mi < 4; ++mi)
#pragma unroll
                for (int ni = 0; ni < 4; ++ni)
                    mma16816(acc[mi][ni], ah[mi], &bh[ni >> 1][(ni & 1) * 2]);
#pragma unroll
            for (int mi = 0; mi < 4; ++mi) LDSM4(al[mi], sAl + aso[mi]);
#pragma unroll
            for (int mi = 0; mi < 4; ++mi)
#pragma unroll
                for (int ni = 0; ni < 4; ++ni)
                    mma16816(acc[mi][ni], al[mi], &bh[ni >> 1][(ni & 1) * 2]);
#pragma unroll
            for (int g = 0; g < 2; ++g) LDSM4(bl[g], sBl + bso[g]);
#pragma unroll
            for (int mi = 0; mi < 4; ++mi)
#pragma unroll
                for (int ni = 0; ni < 4; ++ni)
                    mma16816(acc[mi][ni], ah[mi], &bl[ni >> 1][(ni & 1) * 2]);
        }
    }
    CP_WAITALL();

    int row0 = mbase + wm * 64 + (lane >> 2);
    int col0 = nbase + wn * 32 + 2 * (lane & 3);
#pragma unroll
    for (int mi = 0; mi < 4; ++mi) {
#pragma unroll
        for (int ni = 0; ni < 4; ++ni) {
            int r = row0 + mi * 16;
            int c = col0 + ni * 8;
            float2 v;
            v.x = acc[mi][ni][0]; v.y = acc[mi][ni][1];
            *(float2*)(X + (size_t)r * OC + c) = v;
            v.x = acc[mi][ni][2]; v.y = acc[mi][ni][3];
            *(float2*)(X + (size_t)(r + 8) * OC + c) = v;
        }
    }
}

// ---------------- stats ----------------
__global__ void stats_kernel(const float* __restrict__ Xp,
                             const int* __restrict__ plens) {
    int c = threadIdx.x;
    int chunk = blockIdx.x;
    int r0 = chunk * 128;
    int b = r0 >> 12;
    int lim = plens[b] - (r0 & 4095);
    int nv = lim < 0 ? 0 : (lim > 128 ? 128 : lim);
    const float* p = Xp + (size_t)r0 * DD2 + c;
    float s = 0.0f, s2 = 0.0f;
    for (int r = 0; r < nv; ++r) {
        float x = p[(size_t)r * DD2];
        s += x;
        s2 = __fmaf_rn(x, x, s2);
    }
    g_part[(size_t)chunk * 768 + c] = s;
    g_part[(size_t)chunk * 768 + 384 + c] = s2;
}

__global__ void finalize_kernel(const float* __restrict__ gamma,
                                const float* __restrict__ beta,
                                const int* __restrict__ plens, int layer) {
    int c = blockIdx.x;    // 384 blocks
    int t = threadIdx.x;   // 128 threads
    float s = 0.0f, s2 = 0.0f;
    for (int i = t; i < 512; i += 128) {
        s  += g_part[(size_t)i * 768 + c];
        s2 += g_part[(size_t)i * 768 + 384 + c];
    }
    __shared__ float bs[128], bs2[128];
    bs[t] = s; bs2[t] = s2;
    __syncthreads();
    for (int o = 64; o > 0; o >>= 1) {
        if (t < o) { bs[t] += bs[t + o]; bs2[t] += bs2[t + o]; }
        __syncthreads();
    }
    if (t == 0) {
        float nf = 0.0f;
        for (int b = 0; b < BB; ++b) nf += (float)plens[b];
        nf = fmaxf(nf, 1.0f);
        float mean = bs[0] / nf;
        float var = bs2[0] / nf - mean * mean;
        var = fmaxf(var, 0.0f);
        float rs = rsqrtf(var + 1e-5f);
        float sc = gamma[c] * rs;
        g_scale[layer * DD2 + c] = sc;
        g_shift[layer * DD2 + c] = beta[c] - mean * sc;
    }
}

// ---------------- BN+GELU -> bf16 split activations ----------------------
__global__ void bn_gelu_split_kernel(const float* __restrict__ Xp,
                                     const int* __restrict__ plens) {
    size_t i4 = ((size_t)blockIdx.x * blockDim.x + threadIdx.x) * 4;
    if (i4 >= X_ELEMS) return;
    int row = (int)(i4 / DD2);
    int c = (int)(i4 % DD2);
    bool valid = (row & 4095) < plens[row >> 12];
    const float* sc = g_scale + c;
    const float* sh = g_shift + c;
    float4 x = *(const float4*)(Xp + i4);
    float y0 = 0.f, y1 = 0.f, y2 = 0.f, y3 = 0.f;
    if (valid) {
        y0 = gelu_exact(__fmaf_rn(x.x, sc[0], sh[0]));
        y1 = gelu_exact(__fmaf_rn(x.y, sc[1], sh[1]));
        y2 = gelu_exact(__fmaf_rn(x.z, sc[2], sh[2]));
        y3 = gelu_exact(__fmaf_rn(x.w, sc[3], sh[3]));
    }
    __nv_bfloat16 h0, l0, h1, l1, h2, l2, h3, l3;
    split_bf16(y0, h0, l0); split_bf16(y1, h1, l1);
    split_bf16(y2, h2, l2); split_bf16(y3, h3, l3);
    size_t o = (size_t)row * KPAD + c;
    __nv_bfloat162* ph = (__nv_bfloat162*)(g_Ah + o);
    __nv_bfloat162* pl = (__nv_bfloat162*)(g_Al + o);
    ph[0] = __nv_bfloat162{h0, h1}; ph[1] = __nv_bfloat162{h2, h3};
    pl[0] = __nv_bfloat162{l0, l1}; pl[1] = __nv_bfloat162{l2, l3};
}

// ---------------- final masked BN (fp32, in place) -----------------------
__global__ void bn_final_kernel(float* __restrict__ Y,
                                const int* __restrict__ plens) {
    size_t i4 = ((size_t)blockIdx.x * blockDim.x + threadIdx.x) * 4;
    if (i4 >= X_ELEMS) return;
    int row = (int)(i4 / DD2);
    int c = (int)(i4 % DD2);
    bool valid = (row & 4095) < plens[row >> 12];
    const float* sc = g_scale + DD2 + c;
    const float* sh = g_shift + DD2 + c;
    float4 x = *(const float4*)(Y + i4);
    float4 y;
    if (valid) {
        y.x = __fmaf_rn(x.x, sc[0], sh[0]);
        y.y = __fmaf_rn(x.y, sc[1], sh[1]);
        y.z = __fmaf_rn(x.z, sc[2], sh[2]);
        y.w = __fmaf_rn(x.w, sc[3], sh[3]);
    } else {
        y.x = y.y = y.z = y.w = 0.0f;
    }
    *(float4*)(Y + i4) = y;
}

// ---------------- launch ----------------
extern "C" void kernel_launch(void* const* d_in, const int* in_sizes, int n_in,
                              void* d_out, int out_size) {
    const float* xyz1    = (const float*)d_in[0];
    const float* xyz2    = (const float*)d_in[1];
    const float* points1 = (const float*)d_in[2];
    const float* points2 = (const float*)d_in[3];
    const int*   plens   = (const int*)d_in[4];
    const int*   elens   = (const int*)d_in[5];
    const float* W0 = (const float*)d_in[7];
    const float* g0 = (const float*)d_in[8];
    const float* b0 = (const float*)d_in[9];
    const float* W1 = (const float*)d_in[10];
    const float* g1 = (const float*)d_in[11];
    const float* b1 = (const float*)d_in[12];
    float* out = (float*)d_out;

    __nv_bfloat16 *pAh, *pAl, *pW0h, *pW0l, *pW1h, *pW1l;
    float* pX0;
    cudaGetSymbolAddress((void**)&pAh, g_Ah);
    cudaGetSymbolAddress((void**)&pAl, g_Al);
    cudaGetSymbolAddress((void**)&pX0, g_X0);
    cudaGetSymbolAddress((void**)&pW0h, g_W0h);
    cudaGetSymbolAddress((void**)&pW0l, g_W0l);
    cudaGetSymbolAddress((void**)&pW1h, g_W1h);
    cudaGetSymbolAddress((void**)&pW1l, g_W1l);

    cudaFuncSetAttribute(gemm_mma_kernel,
                         cudaFuncAttributeMaxDynamicSharedMemorySize, GEMM_SMEM);

    prep_weights_kernel<<<(OC * KPAD + 255) / 256, 256>>>(W0, W1);
    knn_kernel<<<dim3(NN / 256, BB), 256>>>(xyz1, xyz2, elens, out + X_ELEMS);
    interp_kernel<<<MM / 8, 256>>>(points1, points2);

    // layer 0: X0 = new_points @ W0^T  (K = 448 padded)
    gemm_mma_kernel<<<dim3(3, MM / 128), 256, GEMM_SMEM>>>(pAh, pAl, pW0h, pW0l, pX0, 448);
    stats_kernel<<<512, 384>>>(pX0, plens);
    finalize_kernel<<<384, 128>>>(g0, b0, plens, 0);
    bn_gelu_split_kernel<<<(unsigned)(X_ELEMS / 4 + 255) / 256, 256>>>(pX0, plens);

    // layer 1: out = act @ W1^T  (K = 384)
    gemm_mma_kernel<<<dim3(3, MM / 128), 256, GEMM_SMEM>>>(pAh, pAl, pW1h, pW1l, out, 384);
    stats_kernel<<<512, 384>>>(out, plens);
    finalize_kernel<<<384, 128>>>(g1, b1, plens, 1);
    bn_final_kernel<<<(unsigned)(X_ELEMS / 4 + 255) / 256, 256>>>(out, plens);
}

// round 7
// speedup vs baseline: 3.0751x; 1.1822x over previous
#include <cuda_runtime.h>
#include <cuda_bf16.h>
#include <math.h>
#include <stdint.h>

// ---------------- problem constants ----------------
#define BB   16
#define NN   4096
#define SS   512
#define DD2  384
#define KNN  5
#define MM   (BB*NN)          // 65536 rows
#define KPAD 416              // padded K stride (bf16 arrays), 13*32, covers 387
#define OC   384              // output channels
#define X_ELEMS ((size_t)MM*DD2)   // 25165824
#define EPSF 1.1920929e-7f

// K-order permutation: k 0..383 = interpolated feature k, k 384..386 = xyz, 387.. = 0.
// Weights permuted identically, so the GEMM result is unchanged.

// ---------------- device scratch (static, no allocation) ----------------
__device__ __align__(128) __nv_bfloat16 g_Ah[(size_t)MM * KPAD];
__device__ __align__(128) __nv_bfloat16 g_Al[(size_t)MM * KPAD];
__device__ __align__(128) float g_X0[(size_t)MM * DD2];
__device__ __align__(128) __nv_bfloat16 g_W0h[OC * KPAD];
__device__ __align__(128) __nv_bfloat16 g_W0l[OC * KPAD];
__device__ __align__(128) __nv_bfloat16 g_W1h[OC * KPAD];
__device__ __align__(128) __nv_bfloat16 g_W1l[OC * KPAD];
__device__ int   g_idx[MM * KNN];
__device__ float g_w[MM * KNN];
__device__ float g_part[512 * 2 * DD2];
__device__ float g_scale[2 * DD2];
__device__ float g_shift[2 * DD2];

// ---------------- helpers ----------------
__device__ __forceinline__ uint32_t smem_u32(const void* p) {
    uint32_t a;
    asm("{ .reg .u64 t; cvta.to.shared.u64 t, %1; cvt.u32.u64 %0, t; }" : "=r"(a) : "l"(p));
    return a;
}
__device__ __forceinline__ void cp16(uint32_t s, const void* g) {
    asm volatile("cp.async.cg.shared.global [%0], [%1], 16;" :: "r"(s), "l"(g));
}
#define CP_COMMIT() asm volatile("cp.async.commit_group;")
#define CP_WAIT1()  asm volatile("cp.async.wait_group 1;")
#define CP_WAIT0()  asm volatile("cp.async.wait_group 0;")

#define LDSM4(r, addr) \
    asm volatile("ldmatrix.sync.aligned.m8n8.x4.shared.b16 {%0,%1,%2,%3}, [%4];" \
        : "=r"((r)[0]), "=r"((r)[1]), "=r"((r)[2]), "=r"((r)[3]) : "r"(addr))

__device__ __forceinline__ void mma16816(float* c, const uint32_t* a, const uint32_t* b) {
    asm volatile(
        "mma.sync.aligned.m16n8k16.row.col.f32.bf16.bf16.f32 "
        "{%0,%1,%2,%3}, {%4,%5,%6,%7}, {%8,%9}, {%0,%1,%2,%3};"
        : "+f"(c[0]), "+f"(c[1]), "+f"(c[2]), "+f"(c[3])
        : "r"(a[0]), "r"(a[1]), "r"(a[2]), "r"(a[3]), "r"(b[0]), "r"(b[1]));
}

__device__ __forceinline__ float gelu_exact(float v) {
    return 0.5f * v * (1.0f + erff(v * 0.7071067811865476f));
}
__device__ __forceinline__ void split_bf16(float v, __nv_bfloat16 &h, __nv_bfloat16 &l) {
    h = __float2bfloat16(v);
    l = __float2bfloat16(v - __bfloat162float(h));
}

// ---------------- weight prep: permute + split + pad ----------------
__global__ void prep_weights_kernel(const float* __restrict__ W0,
                                    const float* __restrict__ W1) {
    int i = blockIdx.x * blockDim.x + threadIdx.x;
    if (i >= OC * KPAD) return;
    int o = i / KPAD, k = i % KPAD;
    float v0 = 0.0f, v1 = 0.0f;
    if (k < 384)      v0 = W0[o * 387 + 3 + k];     // feature part
    else if (k < 387) v0 = W0[o * 387 + (k - 384)]; // xyz part
    if (k < 384)      v1 = W1[o * 384 + k];
    __nv_bfloat16 h, l;
    split_bf16(v0, h, l); g_W0h[i] = h; g_W0l[i] = l;
    split_bf16(v1, h, l); g_W1h[i] = h; g_W1l[i] = l;
}

// ---------------- KNN ----------------
__global__ void knn_kernel(const float* __restrict__ xyz1,
                           const float* __restrict__ xyz2,
                           const int* __restrict__ elens,
                           float* __restrict__ out_idx) {
    __shared__ float sx[SS], sy[SS], sz[SS];
    int b = blockIdx.y;
    const float* x2 = xyz2 + (size_t)b * SS * 3;
    for (int i = threadIdx.x; i < SS; i += blockDim.x) {
        sx[i] = x2[i * 3 + 0]; sy[i] = x2[i * 3 + 1]; sz[i] = x2[i * 3 + 2];
    }
    __syncthreads();
    int n = blockIdx.x * blockDim.x + threadIdx.x;
    int row = b * NN + n;
    float px = xyz1[(size_t)row * 3 + 0];
    float py = xyz1[(size_t)row * 3 + 1];
    float pz = xyz1[(size_t)row * 3 + 2];
    int sv = elens[b];
    float b0 = 1e30f, b1 = 1e30f, b2 = 1e30f, b3 = 1e30f, b4 = 1e30f;
    int j0 = 0, j1 = 0, j2 = 0, j3 = 0, j4 = 0;
    for (int s = 0; s < sv; ++s) {
        float dx = px - sx[s], dy = py - sy[s], dz = pz - sz[s];
        float d = __fmaf_rn(dz, dz, __fmaf_rn(dy, dy, dx * dx));
        if (d < b4) {
            if (d < b3) {
                b4 = b3; j4 = j3;
                if (d < b2) {
                    b3 = b2; j3 = j2;
                    if (d < b1) {
                        b2 = b1; j2 = j1;
                        if (d < b0) { b1 = b0; j1 = j0; b0 = d; j0 = s; }
                        else        { b1 = d;  j1 = s; }
                    } else { b2 = d; j2 = s; }
                } else { b3 = d; j3 = s; }
            } else { b4 = d; j4 = s; }
        }
    }
    float r0 = 1.0f / (b0 + EPSF), r1 = 1.0f / (b1 + EPSF), r2 = 1.0f / (b2 + EPSF);
    float r3 = 1.0f / (b3 + EPSF), r4 = 1.0f / (b4 + EPSF);
    float rsum = r0 + r1 + r2 + r3 + r4;
    size_t base = (size_t)row * KNN;
    g_idx[base + 0] = j0; g_idx[base + 1] = j1; g_idx[base + 2] = j2;
    g_idx[base + 3] = j3; g_idx[base + 4] = j4;
    g_w[base + 0] = r0 / rsum; g_w[base + 1] = r1 / rsum; g_w[base + 2] = r2 / rsum;
    g_w[base + 3] = r3 / rsum; g_w[base + 4] = r4 / rsum;
    out_idx[base + 0] = (float)j0; out_idx[base + 1] = (float)j1;
    out_idx[base + 2] = (float)j2; out_idx[base + 3] = (float)j3;
    out_idx[base + 4] = (float)j4;
}

// ---------------- interpolation + concat -> g_Ah/g_Al (bf16 split) -------
__global__ void interp_kernel(const float* __restrict__ points1,
                              const float* __restrict__ points2) {
    int gwarp = (blockIdx.x * blockDim.x + threadIdx.x) >> 5;
    int lane = threadIdx.x & 31;
    if (gwarp >= MM) return;
    int row = gwarp;
    int b = row >> 12;
    const int* ip = g_idx + (size_t)row * KNN;
    const float* wp = g_w + (size_t)row * KNN;
    int i0 = ip[0], i1 = ip[1], i2 = ip[2], i3 = ip[3], i4 = ip[4];
    float w0 = wp[0], w1 = wp[1], w2 = wp[2], w3 = wp[3], w4 = wp[4];
    const float* p2 = points2 + (size_t)b * SS * DD2;
    const float2* r0 = (const float2*)(p2 + (size_t)i0 * DD2);
    const float2* r1 = (const float2*)(p2 + (size_t)i1 * DD2);
    const float2* r2 = (const float2*)(p2 + (size_t)i2 * DD2);
    const float2* r3 = (const float2*)(p2 + (size_t)i3 * DD2);
    const float2* r4 = (const float2*)(p2 + (size_t)i4 * DD2);
    __nv_bfloat16* oh = g_Ah + (size_t)row * KPAD;
    __nv_bfloat16* ol = g_Al + (size_t)row * KPAD;
    __nv_bfloat162* oh2 = (__nv_bfloat162*)oh;
    __nv_bfloat162* ol2 = (__nv_bfloat162*)ol;
#pragma unroll
    for (int cc = 0; cc < 6; ++cc) {
        int c2 = cc * 32 + lane;        // float2 index: cols 2*c2, 2*c2+1
        float2 v0 = r0[c2], v1 = r1[c2], v2 = r2[c2], v3 = r3[c2], v4 = r4[c2];
        float ax = w0 * v0.x; ax = __fmaf_rn(w1, v1.x, ax); ax = __fmaf_rn(w2, v2.x, ax);
        ax = __fmaf_rn(w3, v3.x, ax); ax = __fmaf_rn(w4, v4.x, ax);
        float ay = w0 * v0.y; ay = __fmaf_rn(w1, v1.y, ay); ay = __fmaf_rn(w2, v2.y, ay);
        ay = __fmaf_rn(w3, v3.y, ay); ay = __fmaf_rn(w4, v4.y, ay);
        __nv_bfloat16 hx, lx, hy, ly;
        split_bf16(ax, hx, lx); split_bf16(ay, hy, ly);
        oh2[c2] = __nv_bfloat162{hx, hy};
        ol2[c2] = __nv_bfloat162{lx, ly};
    }
    if (lane < 3) {   // xyz at k = 384..386
        float v = points1[(size_t)row * 3 + lane];
        __nv_bfloat16 h, l; split_bf16(v, h, l);
        oh[384 + lane] = h; ol[384 + lane] = l;
    }
    for (int c = 387 + lane; c < KPAD; c += 32) {
        oh[c] = __float2bfloat16(0.0f); ol[c] = __float2bfloat16(0.0f);
    }
}

// ---------------- bf16x3 GEMM via mma.sync + fused masked stats ----------
// C[M,384] = A[M,nk] * B^T.  CTA tile 128x128, warp 64x32, KC=32, 2 stages.
#define STAGE_SZ 32768
#define GEMM_SMEM (2*STAGE_SZ)

__global__ __launch_bounds__(256, 2)
void gemm_mma_kernel(const __nv_bfloat16* __restrict__ Ahp,
                     const __nv_bfloat16* __restrict__ Alp,
                     const __nv_bfloat16* __restrict__ Bhp,
                     const __nv_bfloat16* __restrict__ Blp,
                     float* __restrict__ X, int nk,
                     const int* __restrict__ plens) {
    extern __shared__ __align__(128) char smem[];
    uint32_t sb = smem_u32(smem);
    int tid = threadIdx.x, lane = tid & 31, wid = tid >> 5;
    int wm = wid & 1, wn = wid >> 1;
    int mbase = blockIdx.y * 128, nbase = blockIdx.x * 128;
    int nst = nk >> 5;

    int lrow = tid >> 2, lc = tid & 3;

    auto load_stage = [&](int st) {
        uint32_t sA = sb + (st & 1) * STAGE_SZ;
        int kb = st * 32;
#pragma unroll
        for (int i = 0; i < 2; ++i) {
            int row = lrow + i * 64;
            uint32_t so = row * 64 + ((uint32_t)(lc ^ ((row >> 1) & 3)) << 4);
            size_t ga = (size_t)(mbase + row) * KPAD + kb + lc * 8;
            size_t gb = (size_t)(nbase + row) * KPAD + kb + lc * 8;
            cp16(sA + so,         Ahp + ga);
            cp16(sA + 8192 + so,  Alp + ga);
            cp16(sA + 16384 + so, Bhp + gb);
            cp16(sA + 24576 + so, Blp + gb);
        }
    };

    float acc[4][4][4] = {};

    load_stage(0); CP_COMMIT();

    int arow = lane & 15;            // A: row within m16 tile
    int ahalf = lane >> 4;           // A: k-chunk half
    int brow = (lane & 7) + ((lane >> 4) << 3);  // B: n within 16
    int bhalf = (lane >> 3) & 1;     // B: k-chunk half

    for (int st = 0; st < nst; ++st) {
        if (st + 1 < nst) { load_stage(st + 1); CP_COMMIT(); CP_WAIT1(); }
        else              { CP_WAIT0(); }
        __syncthreads();
        uint32_t sA = sb + (st & 1) * STAGE_SZ;
        uint32_t sAl = sA + 8192, sB = sA + 16384, sBl = sA + 24576;
#pragma unroll
        for (int k2 = 0; k2 < 2; ++k2) {
            int cbase = 2 * k2;
            uint32_t ah[4][4], bh[2][4], bl[2][4];
            uint32_t aso[4], bso[2];
#pragma unroll
            for (int mi = 0; mi < 4; ++mi) {
                int row = wm * 64 + mi * 16 + arow;
                aso[mi] = row * 64 + ((uint32_t)((cbase + ahalf) ^ ((row >> 1) & 3)) << 4);
                LDSM4(ah[mi], sA + aso[mi]);
            }
#pragma unroll
            for (int g = 0; g < 2; ++g) {
                int row = wn * 32 + g * 16 + brow;
                bso[g] = row * 64 + ((uint32_t)((cbase + bhalf) ^ ((row >> 1) & 3)) << 4);
                LDSM4(bh[g], sB + bso[g]);
            }
            // A_hi * B_hi
#pragma unroll
            for (int mi = 0; mi < 4; ++mi)
#pragma unroll
                for (int ni = 0; ni < 4; ++ni)
                    mma16816(acc[mi][ni], ah[mi], &bh[ni >> 1][(ni & 1) * 2]);
            // A_hi * B_lo
#pragma unroll
            for (int g = 0; g < 2; ++g) LDSM4(bl[g], sBl + bso[g]);
#pragma unroll
            for (int mi = 0; mi < 4; ++mi)
#pragma unroll
                for (int ni = 0; ni < 4; ++ni)
                    mma16816(acc[mi][ni], ah[mi], &bl[ni >> 1][(ni & 1) * 2]);
            // A_lo * B_hi  (reuse ah registers for A_lo)
#pragma unroll
            for (int mi = 0; mi < 4; ++mi) LDSM4(ah[mi], sAl + aso[mi]);
#pragma unroll
            for (int mi = 0; mi < 4; ++mi)
#pragma unroll
                for (int ni = 0; ni < 4; ++ni)
                    mma16816(acc[mi][ni], ah[mi], &bh[ni >> 1][(ni & 1) * 2]);
        }
        __syncthreads();
    }

    // ---- output store ----
    int row0 = mbase + wm * 64 + (lane >> 2);
    int col0 = nbase + wn * 32 + 2 * (lane & 3);
#pragma unroll
    for (int mi = 0; mi < 4; ++mi) {
#pragma unroll
        for (int ni = 0; ni < 4; ++ni) {
            int r = row0 + mi * 16;
            int c = col0 + ni * 8;
            float2 v;
            v.x = acc[mi][ni][0]; v.y = acc[mi][ni][1];
            *(float2*)(X + (size_t)r * OC + c) = v;
            v.x = acc[mi][ni][2]; v.y = acc[mi][ni][3];
            *(float2*)(X + (size_t)(r + 8) * OC + c) = v;
        }
    }

    // ---- fused masked stats: per-column sum / sumsq for this 128-row chunk ----
    float* sbuf = (float*)smem;     // 256 floats: [0..127]=sum, [128..255]=sumsq
    __syncthreads();                // mainloop smem reads done (already synced), reuse
    sbuf[tid < 256 ? tid : 0] = 0.0f;
    __syncthreads();

    int bidx = mbase >> 12;
    int lim = plens[bidx] - (mbase & 4095);
    int nv = lim < 0 ? 0 : (lim > 128 ? 128 : lim);
    int ritb = wm * 64 + (lane >> 2);

    float csum[8], csq[8];
#pragma unroll
    for (int t = 0; t < 8; ++t) { csum[t] = 0.0f; csq[t] = 0.0f; }
#pragma unroll
    for (int mi = 0; mi < 4; ++mi) {
#pragma unroll
        for (int j = 0; j < 2; ++j) {
            bool v = (ritb + mi * 16 + 8 * j) < nv;
            if (v) {
#pragma unroll
                for (int ni = 0; ni < 4; ++ni) {
                    float a0 = acc[mi][ni][2 * j + 0];
                    float a1 = acc[mi][ni][2 * j + 1];
                    csum[2 * ni + 0] += a0;
                    csq[2 * ni + 0] = __fmaf_rn(a0, a0, csq[2 * ni + 0]);
                    csum[2 * ni + 1] += a1;
                    csq[2 * ni + 1] = __fmaf_rn(a1, a1, csq[2 * ni + 1]);
                }
            }
        }
    }
#pragma unroll
    for (int m = 4; m <= 16; m <<= 1) {
#pragma unroll
        for (int t = 0; t < 8; ++t) {
            csum[t] += __shfl_xor_sync(0xFFFFFFFFu, csum[t], m);
            csq[t]  += __shfl_xor_sync(0xFFFFFFFFu, csq[t], m);
        }
    }
    if (lane < 4) {
#pragma unroll
        for (int ni = 0; ni < 4; ++ni) {
#pragma unroll
            for (int j = 0; j < 2; ++j) {
                int col = wn * 32 + ni * 8 + 2 * lane + j;
                atomicAdd(&sbuf[col], csum[2 * ni + j]);
                atomicAdd(&sbuf[128 + col], csq[2 * ni + j]);
            }
        }
    }
    __syncthreads();
    int chunk = blockIdx.y;
    if (tid < 128)       g_part[(size_t)chunk * 768 + nbase + tid] = sbuf[tid];
    else if (tid < 256)  g_part[(size_t)chunk * 768 + 384 + nbase + (tid - 128)] = sbuf[tid];
}

// ---------------- finalize: mean/var -> scale/shift ----------------------
__global__ void finalize_kernel(const float* __restrict__ gamma,
                                const float* __restrict__ beta,
                                const int* __restrict__ plens, int layer) {
    int c = blockIdx.x;    // 384 blocks
    int t = threadIdx.x;   // 128 threads
    float s = 0.0f, s2 = 0.0f;
    for (int i = t; i < 512; i += 128) {
        s  += g_part[(size_t)i * 768 + c];
        s2 += g_part[(size_t)i * 768 + 384 + c];
    }
    __shared__ float bs[128], bs2[128];
    bs[t] = s; bs2[t] = s2;
    __syncthreads();
    for (int o = 64; o > 0; o >>= 1) {
        if (t < o) { bs[t] += bs[t + o]; bs2[t] += bs2[t + o]; }
        __syncthreads();
    }
    if (t == 0) {
        float nf = 0.0f;
        for (int b = 0; b < BB; ++b) nf += (float)plens[b];
        nf = fmaxf(nf, 1.0f);
        float mean = bs[0] / nf;
        float var = bs2[0] / nf - mean * mean;
        var = fmaxf(var, 0.0f);
        float rs = rsqrtf(var + 1e-5f);
        float sc = gamma[c] * rs;
        g_scale[layer * DD2 + c] = sc;
        g_shift[layer * DD2 + c] = beta[c] - mean * sc;
    }
}

// ---------------- BN+GELU -> bf16 split activations ----------------------
__global__ void bn_gelu_split_kernel(const float* __restrict__ Xp,
                                     const int* __restrict__ plens) {
    size_t i4 = ((size_t)blockIdx.x * blockDim.x + threadIdx.x) * 4;
    if (i4 >= X_ELEMS) return;
    int row = (int)(i4 / DD2);
    int c = (int)(i4 % DD2);
    bool valid = (row & 4095) < plens[row >> 12];
    const float* sc = g_scale + c;
    const float* sh = g_shift + c;
    float4 x = *(const float4*)(Xp + i4);
    float y0 = 0.f, y1 = 0.f, y2 = 0.f, y3 = 0.f;
    if (valid) {
        y0 = gelu_exact(__fmaf_rn(x.x, sc[0], sh[0]));
        y1 = gelu_exact(__fmaf_rn(x.y, sc[1], sh[1]));
        y2 = gelu_exact(__fmaf_rn(x.z, sc[2], sh[2]));
        y3 = gelu_exact(__fmaf_rn(x.w, sc[3], sh[3]));
    }
    __nv_bfloat16 h0, l0, h1, l1, h2, l2, h3, l3;
    split_bf16(y0, h0, l0); split_bf16(y1, h1, l1);
    split_bf16(y2, h2, l2); split_bf16(y3, h3, l3);
    size_t o = (size_t)row * KPAD + c;
    __nv_bfloat162* ph = (__nv_bfloat162*)(g_Ah + o);
    __nv_bfloat162* pl = (__nv_bfloat162*)(g_Al + o);
    ph[0] = __nv_bfloat162{h0, h1}; ph[1] = __nv_bfloat162{h2, h3};
    pl[0] = __nv_bfloat162{l0, l1}; pl[1] = __nv_bfloat162{l2, l3};
}

// ---------------- final masked BN (fp32, in place) -----------------------
__global__ void bn_final_kernel(float* __restrict__ Y,
                                const int* __restrict__ plens) {
    size_t i4 = ((size_t)blockIdx.x * blockDim.x + threadIdx.x) * 4;
    if (i4 >= X_ELEMS) return;
    int row = (int)(i4 / DD2);
    int c = (int)(i4 % DD2);
    bool valid = (row & 4095) < plens[row >> 12];
    const float* sc = g_scale + DD2 + c;
    const float* sh = g_shift + DD2 + c;
    float4 x = *(const float4*)(Y + i4);
    float4 y;
    if (valid) {
        y.x = __fmaf_rn(x.x, sc[0], sh[0]);
        y.y = __fmaf_rn(x.y, sc[1], sh[1]);
        y.z = __fmaf_rn(x.z, sc[2], sh[2]);
        y.w = __fmaf_rn(x.w, sc[3], sh[3]);
    } else {
        y.x = y.y = y.z = y.w = 0.0f;
    }
    *(float4*)(Y + i4) = y;
}

// ---------------- launch ----------------
extern "C" void kernel_launch(void* const* d_in, const int* in_sizes, int n_in,
                              void* d_out, int out_size) {
    const float* xyz1    = (const float*)d_in[0];
    const float* xyz2    = (const float*)d_in[1];
    const float* points1 = (const float*)d_in[2];
    const float* points2 = (const float*)d_in[3];
    const int*   plens   = (const int*)d_in[4];
    const int*   elens   = (const int*)d_in[5];
    const float* W0 = (const float*)d_in[7];
    const float* g0 = (const float*)d_in[8];
    const float* b0 = (const float*)d_in[9];
    const float* W1 = (const float*)d_in[10];
    const float* g1 = (const float*)d_in[11];
    const float* b1 = (const float*)d_in[12];
    float* out = (float*)d_out;

    __nv_bfloat16 *pAh, *pAl, *pW0h, *pW0l, *pW1h, *pW1l;
    float* pX0;
    cudaGetSymbolAddress((void**)&pAh, g_Ah);
    cudaGetSymbolAddress((void**)&pAl, g_Al);
    cudaGetSymbolAddress((void**)&pX0, g_X0);
    cudaGetSymbolAddress((void**)&pW0h, g_W0h);
    cudaGetSymbolAddress((void**)&pW0l, g_W0l);
    cudaGetSymbolAddress((void**)&pW1h, g_W1h);
    cudaGetSymbolAddress((void**)&pW1l, g_W1l);

    cudaFuncSetAttribute(gemm_mma_kernel,
                         cudaFuncAttributeMaxDynamicSharedMemorySize, GEMM_SMEM);

    prep_weights_kernel<<<(OC * KPAD + 255) / 256, 256>>>(W0, W1);
    knn_kernel<<<dim3(NN / 256, BB), 256>>>(xyz1, xyz2, elens, out + X_ELEMS);
    interp_kernel<<<MM / 8, 256>>>(points1, points2);

    // layer 0: X0 = new_points @ W0^T  (K = 416 padded), stats fused
    gemm_mma_kernel<<<dim3(3, MM / 128), 256, GEMM_SMEM>>>(pAh, pAl, pW0h, pW0l, pX0, 416, plens);
    finalize_kernel<<<384, 128>>>(g0, b0, plens, 0);
    bn_gelu_split_kernel<<<(unsigned)(X_ELEMS / 4 + 255) / 256, 256>>>(pX0, plens);

    // layer 1: out = act @ W1^T  (K = 384), stats fused
    gemm_mma_kernel<<<dim3(3, MM / 128), 256, GEMM_SMEM>>>(pAh, pAl, pW1h, pW1l, out, 384, plens);
    finalize_kernel<<<384, 128>>>(g1, b1, plens, 1);
    bn_final_kernel<<<(unsigned)(X_ELEMS / 4 + 255) / 256, 256>>>(out, plens);
}